// round 15
// baseline (speedup 1.0000x reference)
#include <cuda_runtime.h>
#include <cuda_bf16.h>
#include <cstdint>
#include <math.h>

// Problem constants
#define SIZE_U   6000
#define SIZE_V   6000
#define N_TOTAL  12000
#define DIM      256
#define KTOP     20
#define ROW_LEN  12000
#define CAP      1024

#define OUT_X    0ull
#define OUT_US   36000000ull
#define OUT_VS   37536000ull

#define NSM      148          // topk CTAs; GEMM CTAs are bids 148..295

// bf16 split scratch + per-row ready flags
__device__ __nv_bfloat16 g_hi[(size_t)N_TOTAL * DIM];
__device__ __nv_bfloat16 g_lo[(size_t)N_TOTAL * DIM];
__device__ int g_flag[N_TOTAL];

__global__ void flag_init_kernel() {
    int i = blockIdx.x * 256 + threadIdx.x;
    if (i < N_TOTAL) g_flag[i] = 0;
}

// ---------------------------------------------------------------------------
// GEMM constants (R12-proven config: CTA 128x128, BK=32, 8 warps of 64x32)
// ---------------------------------------------------------------------------
#define M6    6000
#define GBM   128
#define GBN   128
#define GBK   32
#define NCH   (DIM / GBK)        // 8
#define LDT   40                 // padded smem row stride (bf16)
#define ARRB  (GBM * LDT * 2)    // 10240 B per array
#define STGB  (4 * ARRB)         // 40960 B per stage
#define SMEM_FUSED (2 * STGB)    // 81920 B dynamic smem (GEMM role; topk overlays)
#define NTILE 47                 // ceil(6000/128)
#define NTILES (NTILE * NTILE)   // 2209

struct TopkSmem {
    float cval[CAP];
    int   cidx[CAP];
    float rval[256];
    int   ridx[256];
    float selv[KTOP];
    int   seli[KTOP];
    float wsum;
    int   cnt, word, boolf;
};

__device__ __forceinline__ unsigned ssa(const void* p) {
    return (unsigned)__cvta_generic_to_shared(p);
}
__device__ __forceinline__ void cp16(unsigned dst, const void* src, int bytes) {
    asm volatile("cp.async.cg.shared.global [%0], [%1], 16, %2;"
                 :: "r"(dst), "l"(src), "r"(bytes));
}
__device__ __forceinline__ void cp_commit() {
    asm volatile("cp.async.commit_group;" ::: "memory");
}
template <int N>
__device__ __forceinline__ void cp_wait() {
    asm volatile("cp.async.wait_group %0;" :: "n"(N) : "memory");
}
__device__ __forceinline__ void ldsm4(unsigned addr, unsigned& d0, unsigned& d1,
                                      unsigned& d2, unsigned& d3) {
    asm volatile("ldmatrix.sync.aligned.m8n8.x4.shared.b16 {%0,%1,%2,%3}, [%4];"
                 : "=r"(d0), "=r"(d1), "=r"(d2), "=r"(d3) : "r"(addr));
}
__device__ __forceinline__ void mma16816(float* c, const unsigned* a, unsigned b0, unsigned b1) {
    asm volatile(
        "mma.sync.aligned.m16n8k16.row.col.f32.bf16.bf16.f32 "
        "{%0,%1,%2,%3}, {%4,%5,%6,%7}, {%8,%9}, {%0,%1,%2,%3};"
        : "+f"(c[0]), "+f"(c[1]), "+f"(c[2]), "+f"(c[3])
        : "r"(a[0]), "r"(a[1]), "r"(a[2]), "r"(a[3]), "r"(b0), "r"(b1));
}

// ---------------------------------------------------------------------------
// Topk role: one CTA handles rows {p, 6000+p : p = bid mod 148}. Per row:
// threshold scan + single-pass rank top-20 + weighted merge + bf16 split emit
// + ready-flag release.
// ---------------------------------------------------------------------------
__device__ void topk_row(TopkSmem& S, int n, bool mask_is_bool,
                         const float* __restrict__ u, const float* __restrict__ v,
                         const float* __restrict__ sim, const void* __restrict__ mask,
                         float* __restrict__ out)
{
    const int tid = threadIdx.x;

    bool keep;
    if (mask_is_bool) keep = ((const unsigned char*)mask)[n] != 0;
    else              keep = ((const unsigned*)mask)[n]      != 0;

    const float* feat = (n < SIZE_U) ? (u + (size_t)n * DIM)
                                     : (v + (size_t)(n - SIZE_U) * DIM);
    float* dst = (n < SIZE_U) ? (out + OUT_US + (size_t)n * DIM)
                              : (out + OUT_VS + (size_t)(n - SIZE_U) * DIM);

    float x;
    if (keep) {
        x = feat[tid];
    } else {
        if (tid == 0) S.cnt = 0;
        __syncthreads();

        const float T0 = 0.993f;
        const float4* row4 = (const float4*)(sim + (size_t)n * ROW_LEN);
        for (int i = tid; i < ROW_LEN / 4; i += 256) {
            float4 sv = row4[i];
            if (sv.x > T0) { int p = atomicAdd(&S.cnt, 1); if (p < CAP) { S.cval[p] = sv.x; S.cidx[p] = 4*i;   } }
            if (sv.y > T0) { int p = atomicAdd(&S.cnt, 1); if (p < CAP) { S.cval[p] = sv.y; S.cidx[p] = 4*i+1; } }
            if (sv.z > T0) { int p = atomicAdd(&S.cnt, 1); if (p < CAP) { S.cval[p] = sv.z; S.cidx[p] = 4*i+2; } }
            if (sv.w > T0) { int p = atomicAdd(&S.cnt, 1); if (p < CAP) { S.cval[p] = sv.w; S.cidx[p] = 4*i+3; } }
        }
        __syncthreads();
        const int cnt = S.cnt;

        if (cnt >= KTOP && cnt <= CAP) {
            float myv[4]; int myi[4]; int myrank[4];
            int nown = 0;
            #pragma unroll
            for (int q = 0; q < 4; q++) {
                int c = tid + q * 256;
                if (c < cnt) { myv[q] = S.cval[c]; myi[q] = S.cidx[c]; myrank[q] = 0; nown = q + 1; }
            }
            if (nown > 0) {
                for (int j = 0; j < cnt; j++) {
                    float vj = S.cval[j]; int ij = S.cidx[j];
                    #pragma unroll
                    for (int q = 0; q < 4; q++) {
                        if (q < nown &&
                            (vj > myv[q] || (vj == myv[q] && ij < myi[q]))) myrank[q]++;
                    }
                }
                #pragma unroll
                for (int q = 0; q < 4; q++) {
                    if (q < nown && myrank[q] < KTOP) {
                        S.selv[myrank[q]] = myv[q];
                        S.seli[myrank[q]] = myi[q];
                    }
                }
            }
            __syncthreads();
        } else {
            const float* row = sim + (size_t)n * ROW_LEN;
            for (int j = 0; j < KTOP; j++) {
                float bv = -3e38f; int bi = 0x7fffffff;
                for (int i = tid; i < ROW_LEN; i += 256) {
                    float vv = row[i];
                    bool used = false;
                    for (int q = 0; q < j; q++) if (S.seli[q] == i) used = true;
                    if (!used && (vv > bv || (vv == bv && i < bi))) { bv = vv; bi = i; }
                }
                S.rval[tid] = bv; S.ridx[tid] = bi;
                __syncthreads();
                for (int s = 128; s; s >>= 1) {
                    if (tid < s) {
                        float v2 = S.rval[tid + s]; int i2 = S.ridx[tid + s];
                        if (v2 > S.rval[tid] || (v2 == S.rval[tid] && i2 < S.ridx[tid])) {
                            S.rval[tid] = v2; S.ridx[tid] = i2;
                        }
                    }
                    __syncthreads();
                }
                if (tid == 0) { S.selv[j] = S.rval[0]; S.seli[j] = S.ridx[0]; }
                __syncthreads();
            }
        }

        if (tid == 0) {
            float s = 0.f;
            #pragma unroll
            for (int q = 0; q < KTOP; q++) s += S.selv[q];
            S.wsum = s;
        }
        __syncthreads();

        float acc = 0.f;
        #pragma unroll
        for (int q = 0; q < KTOP; q++) {
            int id = S.seli[q];
            const float* f = (id < SIZE_U) ? (u + (size_t)id * DIM)
                                           : (v + (size_t)(id - SIZE_U) * DIM);
            acc += S.selv[q] * f[tid];
        }
        x = acc / S.wsum;
    }

    dst[tid] = x;
    __nv_bfloat16 h = __float2bfloat16(x);
    g_hi[(size_t)n * DIM + tid] = h;
    g_lo[(size_t)n * DIM + tid] = __float2bfloat16(x - __bfloat162float(h));

    __threadfence();      // per-thread: my stores visible GPU-wide
    __syncthreads();      // all threads' fences done
    if (tid == 0) atomicExch(&g_flag[n], 1);
    __syncthreads();
}

// ---------------------------------------------------------------------------
// GEMM role: R12 128x128 bf16 split-MMA tile, preceded by a spin on the 256
// row-ready flags the tile depends on.
// ---------------------------------------------------------------------------
__device__ void gemm_tile(char* smem, int row0, int col0, float* __restrict__ C)
{
    const unsigned sb = ssa(smem);
    const int tid  = threadIdx.x;
    const int lane = tid & 31;
    const int wid  = tid >> 5;
    const int wr   = (wid >> 2) * 64;
    const int wc   = (wid & 3) * 32;

    // Spin on row readiness: threads 0..127 -> A rows, 128..255 -> B rows.
    {
        int r = -1;
        if (tid < 128) { int a = row0 + tid;       if (a < M6) r = a; }
        else           { int b = col0 + (tid-128); if (b < M6) r = SIZE_U + b; }
        if (r >= 0) {
            volatile int* vf = g_flag;
            while (!vf[r]) __nanosleep(64);
        }
        __threadfence();
        __syncthreads();
    }

    float acc[4][4][4];
    #pragma unroll
    for (int i = 0; i < 4; i++)
        #pragma unroll
        for (int j = 0; j < 4; j++)
            #pragma unroll
            for (int q = 0; q < 4; q++) acc[i][j][q] = 0.f;

    auto load_stage = [&](int st, int kc) {
        const unsigned stbase = sb + st * STGB;
        #pragma unroll
        for (int arr = 0; arr < 4; arr++) {
            const __nv_bfloat16* gsrc = (arr & 1) ? g_lo : g_hi;
            const int rbase = (arr < 2) ? row0 : (SIZE_U + col0);
            const int rlim  = (arr < 2) ? (M6 - row0) : (M6 - col0);
            #pragma unroll
            for (int it = 0; it < 2; it++) {
                int idx = it * 256 + tid;
                int row = idx >> 2;
                int c4  = idx & 3;
                const void* src = gsrc + (size_t)(rbase + row) * DIM + kc + c4 * 8;
                unsigned dst = stbase + arr * ARRB + row * (LDT * 2) + c4 * 16;
                cp16(dst, src, (row < rlim) ? 16 : 0);
            }
        }
        cp_commit();
    };

    load_stage(0, 0);

    for (int c = 0; c < NCH; c++) {
        const int st = c & 1;
        if (c + 1 < NCH) load_stage(st ^ 1, (c + 1) * GBK);
        if (c + 1 < NCH) cp_wait<1>(); else cp_wait<0>();
        __syncthreads();

        const __nv_bfloat16* sAh = (const __nv_bfloat16*)(smem + st * STGB + 0 * ARRB);
        const __nv_bfloat16* sAl = (const __nv_bfloat16*)(smem + st * STGB + 1 * ARRB);
        const __nv_bfloat16* sBh = (const __nv_bfloat16*)(smem + st * STGB + 2 * ARRB);
        const __nv_bfloat16* sBl = (const __nv_bfloat16*)(smem + st * STGB + 3 * ARRB);

        #pragma unroll
        for (int ks = 0; ks < 2; ks++) {
            const int kb = ks * 16;
            unsigned ah[4][4], al[4][4];
            {
                const int arow = (lane & 15);
                const int acol = kb + ((lane & 16) >> 1);
                #pragma unroll
                for (int mf = 0; mf < 4; mf++) {
                    int r = wr + mf * 16 + arow;
                    ldsm4(ssa(sAh + r * LDT + acol), ah[mf][0], ah[mf][1], ah[mf][2], ah[mf][3]);
                    ldsm4(ssa(sAl + r * LDT + acol), al[mf][0], al[mf][1], al[mf][2], al[mf][3]);
                }
            }
            unsigned bh[2][4], bl[2][4];
            {
                const int brow = (lane & 7) + ((lane & 16) >> 1);
                const int bcol = kb + (lane & 8);
                #pragma unroll
                for (int nf2 = 0; nf2 < 2; nf2++) {
                    int r = wc + nf2 * 16 + brow;
                    ldsm4(ssa(sBh + r * LDT + bcol), bh[nf2][0], bh[nf2][1], bh[nf2][2], bh[nf2][3]);
                    ldsm4(ssa(sBl + r * LDT + bcol), bl[nf2][0], bl[nf2][1], bl[nf2][2], bl[nf2][3]);
                }
            }
            #pragma unroll
            for (int mf = 0; mf < 4; mf++)
                #pragma unroll
                for (int nf = 0; nf < 4; nf++) {
                    const int n2 = nf >> 1, h = (nf & 1) * 2;
                    mma16816(acc[mf][nf], ah[mf], bh[n2][h], bh[n2][h + 1]);
                    mma16816(acc[mf][nf], ah[mf], bl[n2][h], bl[n2][h + 1]);
                    mma16816(acc[mf][nf], al[mf], bh[n2][h], bh[n2][h + 1]);
                }
        }
        __syncthreads();
    }

    const int g = lane >> 2, t = lane & 3;
    #pragma unroll
    for (int mf = 0; mf < 4; mf++) {
        int r0 = row0 + wr + mf * 16 + g;
        #pragma unroll
        for (int nf = 0; nf < 4; nf++) {
            int c = col0 + wc + nf * 8 + t * 2;
            if (c >= M6) continue;
            if (r0 < M6) {
                float2 o;
                o.x = __fdividef(1.f, 1.f + __expf(-acc[mf][nf][0]));
                o.y = __fdividef(1.f, 1.f + __expf(-acc[mf][nf][1]));
                *(float2*)(C + (size_t)r0 * M6 + c) = o;
            }
            int r1 = r0 + 8;
            if (r1 < M6) {
                float2 o;
                o.x = __fdividef(1.f, 1.f + __expf(-acc[mf][nf][2]));
                o.y = __fdividef(1.f, 1.f + __expf(-acc[mf][nf][3]));
                *(float2*)(C + (size_t)r1 * M6 + c) = o;
            }
        }
    }
}

// ---------------------------------------------------------------------------
// Fused kernel: bids [0,148) topk role, [148,296) GEMM role.
// Topk bids come first so a residency shortfall degrades to the serial
// schedule instead of deadlocking.
// ---------------------------------------------------------------------------
__global__ __launch_bounds__(256, 2)
void fused_kernel(const float* __restrict__ u, const float* __restrict__ v,
                  const float* __restrict__ sim, const void* __restrict__ mask,
                  float* __restrict__ out)
{
    extern __shared__ char smem[];
    const int bid = blockIdx.x;
    const int tid = threadIdx.x;

    if (bid < NSM) {
        TopkSmem& S = *(TopkSmem*)smem;
        if (tid == 0) { S.word = 0; S.boolf = 0; }
        __syncthreads();
        if (tid < 128) {
            unsigned w = ((const unsigned*)mask)[tid];
            if (w & 0xFEFEFEFEu)        atomicOr(&S.word, 1);
            else if (w & 0xFFFFFF00u)   atomicOr(&S.boolf, 1);
        }
        __syncthreads();
        const bool mask_is_bool = (S.boolf && !S.word);

        // Interleave u/v rows so both GEMM panels become ready progressively.
        for (int p = bid; p < SIZE_U; p += NSM) {
            topk_row(S, p,          mask_is_bool, u, v, sim, mask, out);
            topk_row(S, SIZE_U + p, mask_is_bool, u, v, sim, mask, out);
        }
    } else {
        float* C = out + OUT_X;
        for (int t = bid - NSM; t < NTILES; t += NSM) {
            int row0 = (t / NTILE) * GBM;
            int col0 = (t % NTILE) * GBN;
            gemm_tile(smem, row0, col0, C);
            __syncthreads();
        }
    }
}

// ---------------------------------------------------------------------------
extern "C" void kernel_launch(void* const* d_in, const int* in_sizes, int n_in,
                              void* d_out, int out_size)
{
    const float* u   = (const float*)d_in[0];
    const float* v   = (const float*)d_in[1];
    const float* sim = (const float*)d_in[2];
    const void*  msk = d_in[3];
    float* out = (float*)d_out;

    flag_init_kernel<<<(N_TOTAL + 255) / 256, 256>>>();

    cudaFuncSetAttribute(fused_kernel,
                         cudaFuncAttributeMaxDynamicSharedMemorySize, SMEM_FUSED);
    fused_kernel<<<2 * NSM, 256, SMEM_FUSED>>>(u, v, sim, msk, out);
}